// round 8
// baseline (speedup 1.0000x reference)
#include <cuda_runtime.h>
#include <cuda_fp16.h>
#include <cstdint>
#include <math.h>

constexpr int N = 8192;
constexpr int D = 128;
// features stored pre-scaled by sqrt(10*log2(e)) so Gram = logits*log2(e)
constexpr float PRE_SCALE = 3.79828256f;

constexpr int NT     = 64;
constexpr int NTILES = 2080;
constexpr int GRID   = 148;

constexpr int ROWB  = 272;
constexpr int ATILE = 128 * ROWB;
constexpr int SMEM_A   = 0;
constexpr int SMEM_B0  = ATILE;
constexpr int SMEM_B1  = 2 * ATILE;
constexpr int SMEM_RED = 3 * ATILE;
constexpr int SMEM_BYTES = 3 * ATILE + 2048;

__device__ uint4 g_hv[N * D / 8];
__device__ float g_total[N];
__device__ float g_pos[N];
__device__ float g_loss;
__device__ unsigned g_cnt;
#define G_H ((__half*)g_hv)

__device__ __forceinline__ uint32_t smem_u32(const void* p) {
    uint32_t a;
    asm("{ .reg .u64 t; cvta.to.shared.u64 t, %1; cvt.u32.u64 %0, t; }"
        : "=r"(a) : "l"(p));
    return a;
}
__device__ __forceinline__ void ldmx4(uint32_t& r0, uint32_t& r1, uint32_t& r2,
                                      uint32_t& r3, uint32_t addr) {
    asm volatile("ldmatrix.sync.aligned.m8n8.x4.shared.b16 {%0,%1,%2,%3}, [%4];"
                 : "=r"(r0), "=r"(r1), "=r"(r2), "=r"(r3) : "r"(addr));
}
__device__ __forceinline__ void mma16816(float* c, uint32_t a0, uint32_t a1,
                                         uint32_t a2, uint32_t a3,
                                         uint32_t b0, uint32_t b1) {
    asm volatile(
        "mma.sync.aligned.m16n8k16.row.col.f32.f16.f16.f32 "
        "{%0,%1,%2,%3}, {%4,%5,%6,%7}, {%8,%9}, {%0,%1,%2,%3};"
        : "+f"(c[0]), "+f"(c[1]), "+f"(c[2]), "+f"(c[3])
        : "r"(a0), "r"(a1), "r"(a2), "r"(a3), "r"(b0), "r"(b1));
}
__device__ __forceinline__ float fast_ex2(float x) {
    float r;
    asm("ex2.approx.ftz.f32 %0, %1;" : "=f"(r) : "f"(x));
    return r;
}
__device__ __forceinline__ void cpa16(uint32_t sdst, const void* gsrc) {
    asm volatile("cp.async.cg.shared.global [%0], [%1], 16;"
                 :: "r"(sdst), "l"(gsrc) : "memory");
}
__device__ __forceinline__ void cpa_commit() {
    asm volatile("cp.async.commit_group;" ::: "memory");
}
__device__ __forceinline__ void cpa_wait0() {
    asm volatile("cp.async.wait_group 0;" ::: "memory");
}

__device__ __forceinline__ void stage_tile(uint32_t sdst, const uint4* gsrc, int tid) {
    #pragma unroll
    for (int it = 0; it < 8; it++) {
        int idx = it * 256 + tid;
        int r = idx >> 4, c = idx & 15;
        cpa16(sdst + r * ROWB + c * 16, gsrc + idx);
    }
}

// ---------------- Kernel 1: normalize (pre-scaled fp16) --------------------
__global__ void normalize_kernel(const float* __restrict__ in) {
    const int wid  = threadIdx.x >> 5;
    const int lane = threadIdx.x & 31;
    const int rb   = blockIdx.x * 16 + wid * 2;

    float4 v[2];
    #pragma unroll
    for (int r = 0; r < 2; r++)
        v[r] = ((const float4*)(in + (size_t)(rb + r) * D))[lane];

    float ss[2];
    #pragma unroll
    for (int r = 0; r < 2; r++)
        ss[r] = v[r].x * v[r].x + v[r].y * v[r].y +
                v[r].z * v[r].z + v[r].w * v[r].w;
    #pragma unroll
    for (int o = 16; o; o >>= 1)
        #pragma unroll
        for (int r = 0; r < 2; r++)
            ss[r] += __shfl_xor_sync(0xffffffffu, ss[r], o);

    #pragma unroll
    for (int r = 0; r < 2; r++) {
        float sc = rsqrtf(ss[r]) * PRE_SCALE;
        union { __half2 h[2]; uint2 u; } pk;
        pk.h[0] = __floats2half2_rn(v[r].x * sc, v[r].y * sc);
        pk.h[1] = __floats2half2_rn(v[r].z * sc, v[r].w * sc);
        ((uint2*)g_hv)[(rb + r) * 32 + lane] = pk.u;
    }
    if (lane < 2) { g_total[rb + lane] = 0.f; g_pos[rb + lane] = 0.f; }
    if (blockIdx.x == 0 && threadIdx.x == 0) { g_loss = 0.f; g_cnt = 0u; }
}

// ---------------- Kernel 2: persistent HMMA Gram, A in registers -----------
__global__ __launch_bounds__(256, 1) void gram_kernel() {
    extern __shared__ char smem[];
    const int tid  = threadIdx.x;
    const int lane = tid & 31;
    const int wid  = tid >> 5;
    const int wrow = wid >> 2;
    const int wcol = wid & 3;
    const uint32_t sb = smem_u32(smem);
    float* sred = (float*)(smem + SMEM_RED);

    int t  = (int)((long long)blockIdx.x * NTILES / GRID);
    int t1 = (int)((long long)(blockIdx.x + 1) * NTILES / GRID);
    int br = 0, base = 0;
    while (t >= base + (NT - br)) { base += NT - br; br++; }
    int bc = br + (t - base);

    const uint32_t aLane = (wrow * 64 + (lane & 15)) * ROWB + (lane >> 4) * 16;
    const uint32_t bLane = (wcol * 32 + (lane & 7) + ((lane >> 4) & 1) * 8) * ROWB +
                           ((lane >> 3) & 1) * 16;

    while (t < t1) {
        // ---- segment start: stage A + first B, load A fragments ----
        stage_tile(sb + SMEM_A, (const uint4*)(G_H + (size_t)br * 128 * D), tid);
        stage_tile(sb + SMEM_B0, (const uint4*)(G_H + (size_t)bc * 128 * D), tid);
        cpa_commit(); cpa_wait0();
        __syncthreads();

        uint32_t af[8][4][4];                       // [ks][i][frag]
        #pragma unroll
        for (int ks = 0; ks < 8; ks++)
            #pragma unroll
            for (int i = 0; i < 4; i++)
                ldmx4(af[ks][i][0], af[ks][i][1], af[ks][i][2], af[ks][i][3],
                      sb + SMEM_A + aLane + i * 16 * ROWB + ks * 32);

        float rs_acc[8];
        #pragma unroll
        for (int q = 0; q < 8; q++) rs_acc[q] = 0.f;
        int buf = 0;

        for (;;) {
            const bool diag = (bc == br);
            const bool next_same = (t + 1 < t1) && (bc + 1 < NT);

            // ---- MMA: B frags double-buffered from cur buffer ----
            const uint32_t bbase = sb + (buf ? SMEM_B1 : SMEM_B0) + bLane;
            float acc[4][4][4];
            #pragma unroll
            for (int i = 0; i < 4; i++)
                #pragma unroll
                for (int j = 0; j < 4; j++)
                    #pragma unroll
                    for (int r = 0; r < 4; r++) acc[i][j][r] = 0.f;

            uint32_t bf[2][8];
            ldmx4(bf[0][0], bf[0][1], bf[0][2], bf[0][3], bbase);
            ldmx4(bf[0][4], bf[0][5], bf[0][6], bf[0][7], bbase + 16 * ROWB);
            #pragma unroll
            for (int ks = 0; ks < 8; ks++) {
                const int cur = ks & 1, nxt = cur ^ 1;
                if (ks < 7) {
                    ldmx4(bf[nxt][0], bf[nxt][1], bf[nxt][2], bf[nxt][3],
                          bbase + (ks + 1) * 32);
                    ldmx4(bf[nxt][4], bf[nxt][5], bf[nxt][6], bf[nxt][7],
                          bbase + 16 * ROWB + (ks + 1) * 32);
                }
                #pragma unroll
                for (int i = 0; i < 4; i++)
                    #pragma unroll
                    for (int j = 0; j < 4; j++)
                        mma16816(acc[i][j], af[ks][i][0], af[ks][i][1],
                                 af[ks][i][2], af[ks][i][3],
                                 bf[cur][j * 2], bf[cur][j * 2 + 1]);
            }

            __syncthreads();                        // all warps done with cur buf
            if (next_same) {
                stage_tile(sb + (buf ? SMEM_B0 : SMEM_B1),
                           (const uint4*)(G_H + (size_t)(bc + 1) * 128 * D), tid);
                cpa_commit();
            }

            // ---- epilogue (unsynced: warps drift, MUFU staggers) ----
            const unsigned m = 0xffffffffu;
            if (diag) {
                float rt[8];
                #pragma unroll
                for (int q = 0; q < 8; q++) rt[q] = 0.f;
                #pragma unroll
                for (int i = 0; i < 4; i++)
                    #pragma unroll
                    for (int j = 0; j < 4; j++) {
                        rt[i*2]   += fast_ex2(acc[i][j][0]) + fast_ex2(acc[i][j][1]);
                        rt[i*2+1] += fast_ex2(acc[i][j][2]) + fast_ex2(acc[i][j][3]);
                    }
                #pragma unroll
                for (int q = 0; q < 8; q++) {
                    rt[q] += __shfl_xor_sync(m, rt[q], 1);
                    rt[q] += __shfl_xor_sync(m, rt[q], 2);
                    if ((lane & 3) == 0) rs_acc[q] += rt[q];
                }
                // pos: the 2 warps whose cols fall in this row-half add directly
                if ((lane & 3) == 0 && (wcol >> 1) == wrow) {
                    #pragma unroll
                    for (int i = 0; i < 4; i++)
                        #pragma unroll
                        for (int h = 0; h < 2; h++)
                            atomicAdd(&g_pos[br*128 + wrow*64 + i*16 + (lane>>2) + h*8],
                                      rt[i*2+h]);
                }
            } else {
                float cs[8];
                #pragma unroll
                for (int q = 0; q < 8; q++) cs[q] = 0.f;
                #pragma unroll
                for (int i = 0; i < 4; i++)
                    #pragma unroll
                    for (int j = 0; j < 4; j++) {
                        float e0 = fast_ex2(acc[i][j][0]);
                        float e1 = fast_ex2(acc[i][j][1]);
                        float e2 = fast_ex2(acc[i][j][2]);
                        float e3 = fast_ex2(acc[i][j][3]);
                        rs_acc[i*2]   += e0 + e1;
                        rs_acc[i*2+1] += e2 + e3;
                        cs[j*2]   += e0 + e2;
                        cs[j*2+1] += e1 + e3;
                    }
                #pragma unroll
                for (int q = 0; q < 8; q++) {
                    cs[q] += __shfl_xor_sync(m, cs[q], 4);
                    cs[q] += __shfl_xor_sync(m, cs[q], 8);
                    cs[q] += __shfl_xor_sync(m, cs[q], 16);
                }
                if (lane < 4) {
                    const int colbase = bc * 128 + wcol * 32 + lane * 2;
                    #pragma unroll
                    for (int j = 0; j < 4; j++) {
                        atomicAdd(&g_total[colbase + j * 8],     cs[j*2]);
                        atomicAdd(&g_total[colbase + j * 8 + 1], cs[j*2+1]);
                    }
                }
            }

            t++; bc++;
            if (!next_same) break;
            buf ^= 1;
            cpa_wait0();                            // stage(t) complete before ldsm
        }

        // ---- flush accumulated row sums for band br ----
        const unsigned m = 0xffffffffu;
        float rf[8];
        #pragma unroll
        for (int q = 0; q < 8; q++) {
            float v = rs_acc[q];
            v += __shfl_xor_sync(m, v, 1);
            v += __shfl_xor_sync(m, v, 2);
            rf[q] = v;
        }
        __syncthreads();                            // sred region safe
        if ((lane & 3) == 0) {
            #pragma unroll
            for (int i = 0; i < 4; i++)
                #pragma unroll
                for (int h = 0; h < 2; h++)
                    sred[wcol*128 + wrow*64 + i*16 + (lane>>2) + h*8] = rf[i*2+h];
        }
        __syncthreads();
        if (tid < 128)
            atomicAdd(&g_total[br * 128 + tid],
                      sred[tid] + sred[128+tid] + sred[256+tid] + sred[384+tid]);
        __syncthreads();

        if (t < t1 && bc >= NT) { br++; bc = br; }
    }
}

// ---------------- Kernel 3: parallel loss ----------------------------------
__global__ void loss_kernel(float* __restrict__ out) {
    __shared__ float wsum[8];
    const int r = blockIdx.x * 256 + threadIdx.x;
    float s = __logf(g_total[r]) - __logf(g_pos[r]);
    #pragma unroll
    for (int o = 16; o; o >>= 1) s += __shfl_xor_sync(0xffffffffu, s, o);
    const int lane = threadIdx.x & 31, w = threadIdx.x >> 5;
    if (lane == 0) wsum[w] = s;
    __syncthreads();
    if (threadIdx.x == 0) {
        float bs = 0.f;
        #pragma unroll
        for (int i = 0; i < 8; i++) bs += wsum[i];
        atomicAdd(&g_loss, bs);
        __threadfence();
        unsigned old = atomicAdd(&g_cnt, 1u);
        if (old == gridDim.x - 1) {
            __threadfence();
            float tot = atomicAdd(&g_loss, 0.f);
            out[0] = tot / (float)N;
        }
    }
}

// ---------------- launch ----------------------------------------------------
extern "C" void kernel_launch(void* const* d_in, const int* in_sizes, int n_in,
                              void* d_out, int out_size) {
    const float* feature = (const float*)d_in[0];
    cudaFuncSetAttribute(gram_kernel,
                         cudaFuncAttributeMaxDynamicSharedMemorySize, SMEM_BYTES);
    normalize_kernel<<<N / 16, 256>>>(feature);
    gram_kernel<<<GRID, 256, SMEM_BYTES>>>();
    loss_kernel<<<32, 256>>>((float*)d_out);
}

// round 9
// speedup vs baseline: 1.0981x; 1.0981x over previous
#include <cuda_runtime.h>
#include <cuda_fp16.h>
#include <cstdint>
#include <math.h>

constexpr int N = 8192;
constexpr int D = 128;
constexpr float SCALE_L2E = 14.4269504088896f;   // 10 * log2(e)

constexpr int NT     = 64;
constexpr int NTILES = 2080;
constexpr int GRID   = 296;

constexpr int ROWB  = 272;
constexpr int ATILE = 128 * ROWB;
constexpr int SMEM_A   = 0;
constexpr int SMEM_B0  = ATILE;
constexpr int SMEM_B1  = 2 * ATILE;
constexpr int SMEM_RED = 3 * ATILE;
constexpr int SMEM_BYTES = 3 * ATILE + 2048;

__device__ uint4 g_hv[N * D / 8];
__device__ float g_total[N];
__device__ float g_pos[N];
__device__ float g_loss;
__device__ unsigned g_cnt;
#define G_H ((__half*)g_hv)

__device__ __forceinline__ uint32_t smem_u32(const void* p) {
    uint32_t a;
    asm("{ .reg .u64 t; cvta.to.shared.u64 t, %1; cvt.u32.u64 %0, t; }"
        : "=r"(a) : "l"(p));
    return a;
}
__device__ __forceinline__ void ldmx4(uint32_t& r0, uint32_t& r1, uint32_t& r2,
                                      uint32_t& r3, uint32_t addr) {
    asm volatile("ldmatrix.sync.aligned.m8n8.x4.shared.b16 {%0,%1,%2,%3}, [%4];"
                 : "=r"(r0), "=r"(r1), "=r"(r2), "=r"(r3) : "r"(addr));
}
// fp16-accumulate variant: C/D are 2 regs of packed half2
__device__ __forceinline__ void mma16816h(uint32_t& c0, uint32_t& c1,
                                          uint32_t a0, uint32_t a1,
                                          uint32_t a2, uint32_t a3,
                                          uint32_t b0, uint32_t b1) {
    asm volatile(
        "mma.sync.aligned.m16n8k16.row.col.f16.f16.f16.f16 "
        "{%0,%1}, {%2,%3,%4,%5}, {%6,%7}, {%0,%1};"
        : "+r"(c0), "+r"(c1)
        : "r"(a0), "r"(a1), "r"(a2), "r"(a3), "r"(b0), "r"(b1));
}
__device__ __forceinline__ float fast_ex2(float x) {
    float r;
    asm("ex2.approx.ftz.f32 %0, %1;" : "=f"(r) : "f"(x));
    return r;
}
__device__ __forceinline__ void cpa16(uint32_t sdst, const void* gsrc) {
    asm volatile("cp.async.cg.shared.global [%0], [%1], 16;"
                 :: "r"(sdst), "l"(gsrc) : "memory");
}
__device__ __forceinline__ void cpa_commit() {
    asm volatile("cp.async.commit_group;" ::: "memory");
}
__device__ __forceinline__ void cpa_wait0() {
    asm volatile("cp.async.wait_group 0;" ::: "memory");
}

__device__ __forceinline__ void stage_tile(uint32_t sdst, const uint4* gsrc, int tid) {
    #pragma unroll
    for (int it = 0; it < 8; it++) {
        int idx = it * 256 + tid;
        int r = idx >> 4, c = idx & 15;
        cpa16(sdst + r * ROWB + c * 16, gsrc + idx);
    }
}

// ---------------- Kernel 1: normalize -> fp16 (unscaled) -------------------
__global__ void normalize_kernel(const float* __restrict__ in) {
    const int wid  = threadIdx.x >> 5;
    const int lane = threadIdx.x & 31;
    const int rb   = blockIdx.x * 16 + wid * 2;

    float4 v[2];
    #pragma unroll
    for (int r = 0; r < 2; r++)
        v[r] = ((const float4*)(in + (size_t)(rb + r) * D))[lane];

    float ss[2];
    #pragma unroll
    for (int r = 0; r < 2; r++)
        ss[r] = v[r].x * v[r].x + v[r].y * v[r].y +
                v[r].z * v[r].z + v[r].w * v[r].w;
    #pragma unroll
    for (int o = 16; o; o >>= 1)
        #pragma unroll
        for (int r = 0; r < 2; r++)
            ss[r] += __shfl_xor_sync(0xffffffffu, ss[r], o);

    #pragma unroll
    for (int r = 0; r < 2; r++) {
        float sc = rsqrtf(ss[r]);
        union { __half2 h[2]; uint2 u; } pk;
        pk.h[0] = __floats2half2_rn(v[r].x * sc, v[r].y * sc);
        pk.h[1] = __floats2half2_rn(v[r].z * sc, v[r].w * sc);
        ((uint2*)g_hv)[(rb + r) * 32 + lane] = pk.u;
    }
    if (lane < 2) { g_total[rb + lane] = 0.f; g_pos[rb + lane] = 0.f; }
    if (blockIdx.x == 0 && threadIdx.x == 0) { g_loss = 0.f; g_cnt = 0u; }
}

// ---------------- Kernel 2: persistent HMMA Gram (fp16 accumulate) ---------
__global__ __launch_bounds__(256, 2) void gram_kernel() {
    extern __shared__ char smem[];
    const int tid  = threadIdx.x;
    const int lane = tid & 31;
    const int wid  = tid >> 5;
    const int wrow = wid >> 2;
    const int wcol = wid & 3;
    const uint32_t sb = smem_u32(smem);
    float* sred = (float*)(smem + SMEM_RED);

    int t  = (int)((long long)blockIdx.x * NTILES / GRID);
    int t1 = (int)((long long)(blockIdx.x + 1) * NTILES / GRID);
    int br = 0, base = 0;
    while (t >= base + (NT - br)) { base += NT - br; br++; }
    int bc = br + (t - base);

    uint32_t aAddr[4];
    #pragma unroll
    for (int i = 0; i < 4; i++)
        aAddr[i] = sb + SMEM_A +
                   (wrow * 64 + i * 16 + (lane & 15)) * ROWB + (lane >> 4) * 16;
    const uint32_t bLane = (wcol * 32 + (lane & 7) + ((lane >> 4) & 1) * 8) * ROWB +
                           ((lane >> 3) & 1) * 16;

    while (t < t1) {
        stage_tile(sb + SMEM_A, (const uint4*)(G_H + (size_t)br * 128 * D), tid);
        stage_tile(sb + SMEM_B0, (const uint4*)(G_H + (size_t)bc * 128 * D), tid);
        cpa_commit(); cpa_wait0();
        __syncthreads();

        float rs_acc[8];
        #pragma unroll
        for (int q = 0; q < 8; q++) rs_acc[q] = 0.f;
        int buf = 0;

        for (;;) {
            const bool diag = (bc == br);
            const bool next_same = (t + 1 < t1) && (bc + 1 < NT);
            if (next_same) {
                stage_tile(sb + (buf ? SMEM_B0 : SMEM_B1),
                           (const uint4*)(G_H + (size_t)(bc + 1) * 128 * D), tid);
                cpa_commit();
            }

            const uint32_t bbase = sb + (buf ? SMEM_B1 : SMEM_B0) + bLane;
            uint32_t hacc[4][4][2];                 // packed half2 accumulators
            #pragma unroll
            for (int i = 0; i < 4; i++)
                #pragma unroll
                for (int j = 0; j < 4; j++)
                    hacc[i][j][0] = hacc[i][j][1] = 0u;

            uint32_t bf[2][8];
            ldmx4(bf[0][0], bf[0][1], bf[0][2], bf[0][3], bbase);
            ldmx4(bf[0][4], bf[0][5], bf[0][6], bf[0][7], bbase + 16 * ROWB);
            #pragma unroll
            for (int ks = 0; ks < 8; ks++) {
                const int cur = ks & 1, nxt = cur ^ 1;
                if (ks < 7) {
                    ldmx4(bf[nxt][0], bf[nxt][1], bf[nxt][2], bf[nxt][3],
                          bbase + (ks + 1) * 32);
                    ldmx4(bf[nxt][4], bf[nxt][5], bf[nxt][6], bf[nxt][7],
                          bbase + 16 * ROWB + (ks + 1) * 32);
                }
                #pragma unroll
                for (int i = 0; i < 4; i++) {
                    uint32_t a0, a1, a2, a3;
                    ldmx4(a0, a1, a2, a3, aAddr[i] + ks * 32);
                    #pragma unroll
                    for (int j = 0; j < 4; j++)
                        mma16816h(hacc[i][j][0], hacc[i][j][1],
                                  a0, a1, a2, a3,
                                  bf[cur][j * 2], bf[cur][j * 2 + 1]);
                }
            }

            const unsigned m = 0xffffffffu;
            if (diag) {
                float rt[8];
                #pragma unroll
                for (int q = 0; q < 8; q++) rt[q] = 0.f;
                #pragma unroll
                for (int i = 0; i < 4; i++)
                    #pragma unroll
                    for (int j = 0; j < 4; j++) {
                        float2 p0 = __half22float2(*(__half2*)&hacc[i][j][0]);
                        float2 p1 = __half22float2(*(__half2*)&hacc[i][j][1]);
                        rt[i*2]   += fast_ex2(p0.x * SCALE_L2E) +
                                     fast_ex2(p0.y * SCALE_L2E);
                        rt[i*2+1] += fast_ex2(p1.x * SCALE_L2E) +
                                     fast_ex2(p1.y * SCALE_L2E);
                    }
                #pragma unroll
                for (int q = 0; q < 8; q++) {
                    rt[q] += __shfl_xor_sync(m, rt[q], 1);
                    rt[q] += __shfl_xor_sync(m, rt[q], 2);
                    if ((lane & 3) == 0) rs_acc[q] += rt[q];   // flush re-reduces
                }
                if ((lane & 3) == 0) {
                    #pragma unroll
                    for (int i = 0; i < 4; i++)
                        #pragma unroll
                        for (int h = 0; h < 2; h++)
                            sred[wcol*128 + wrow*64 + i*16 + (lane>>2) + h*8] = rt[i*2+h];
                }
                cpa_wait0();
                __syncthreads();
                if (tid < 128) {
                    int h = tid >> 6;
                    g_pos[br * 128 + tid] =
                        sred[(2*h)*128 + tid] + sred[(2*h+1)*128 + tid];
                }
                __syncthreads();
            } else {
                float cs[8];
                #pragma unroll
                for (int q = 0; q < 8; q++) cs[q] = 0.f;
                #pragma unroll
                for (int i = 0; i < 4; i++)
                    #pragma unroll
                    for (int j = 0; j < 4; j++) {
                        float2 p0 = __half22float2(*(__half2*)&hacc[i][j][0]);
                        float2 p1 = __half22float2(*(__half2*)&hacc[i][j][1]);
                        float e0 = fast_ex2(p0.x * SCALE_L2E);
                        float e1 = fast_ex2(p0.y * SCALE_L2E);
                        float e2 = fast_ex2(p1.x * SCALE_L2E);
                        float e3 = fast_ex2(p1.y * SCALE_L2E);
                        rs_acc[i*2]   += e0 + e1;
                        rs_acc[i*2+1] += e2 + e3;
                        cs[j*2]   += e0 + e2;
                        cs[j*2+1] += e1 + e3;
                    }
                #pragma unroll
                for (int q = 0; q < 8; q++) {
                    cs[q] += __shfl_xor_sync(m, cs[q], 4);
                    cs[q] += __shfl_xor_sync(m, cs[q], 8);
                    cs[q] += __shfl_xor_sync(m, cs[q], 16);
                }
                if (lane < 4) {
                    const int colbase = bc * 128 + wcol * 32 + lane * 2;
                    #pragma unroll
                    for (int j = 0; j < 4; j++) {
                        atomicAdd(&g_total[colbase + j * 8],     cs[j*2]);
                        atomicAdd(&g_total[colbase + j * 8 + 1], cs[j*2+1]);
                    }
                }
                cpa_wait0();
                __syncthreads();
            }

            t++; bc++;
            if (!next_same) break;
            buf ^= 1;
        }

        // flush accumulated row sums for band br
        __syncthreads();
        const unsigned m = 0xffffffffu;
        float rf[8];
        #pragma unroll
        for (int q = 0; q < 8; q++) {
            float v = rs_acc[q];
            v += __shfl_xor_sync(m, v, 1);
            v += __shfl_xor_sync(m, v, 2);
            rf[q] = v;
        }
        if ((lane & 3) == 0) {
            #pragma unroll
            for (int i = 0; i < 4; i++)
                #pragma unroll
                for (int h = 0; h < 2; h++)
                    sred[wcol*128 + wrow*64 + i*16 + (lane>>2) + h*8] = rf[i*2+h];
        }
        __syncthreads();
        if (tid < 128)
            atomicAdd(&g_total[br * 128 + tid],
                      sred[tid] + sred[128+tid] + sred[256+tid] + sred[384+tid]);
        __syncthreads();

        if (t < t1 && bc >= NT) { br++; bc = br; }
    }
}

// ---------------- Kernel 3: parallel loss ----------------------------------
__global__ void loss_kernel(float* __restrict__ out) {
    __shared__ float wsum[8];
    const int r = blockIdx.x * 256 + threadIdx.x;
    float s = __logf(g_total[r]) - __logf(g_pos[r]);
    #pragma unroll
    for (int o = 16; o; o >>= 1) s += __shfl_xor_sync(0xffffffffu, s, o);
    const int lane = threadIdx.x & 31, w = threadIdx.x >> 5;
    if (lane == 0) wsum[w] = s;
    __syncthreads();
    if (threadIdx.x == 0) {
        float bs = 0.f;
        #pragma unroll
        for (int i = 0; i < 8; i++) bs += wsum[i];
        atomicAdd(&g_loss, bs);
        __threadfence();
        unsigned old = atomicAdd(&g_cnt, 1u);
        if (old == gridDim.x - 1) {
            __threadfence();
            float tot = atomicAdd(&g_loss, 0.f);
            out[0] = tot / (float)N;
        }
    }
}

// ---------------- launch ----------------------------------------------------
extern "C" void kernel_launch(void* const* d_in, const int* in_sizes, int n_in,
                              void* d_out, int out_size) {
    const float* feature = (const float*)d_in[0];
    cudaFuncSetAttribute(gram_kernel,
                         cudaFuncAttributeMaxDynamicSharedMemorySize, SMEM_BYTES);
    normalize_kernel<<<N / 16, 256>>>(feature);
    gram_kernel<<<GRID, 256, SMEM_BYTES>>>();
    loss_kernel<<<32, 256>>>((float*)d_out);
}

// round 10
// speedup vs baseline: 1.0990x; 1.0008x over previous
#include <cuda_runtime.h>
#include <cuda_fp16.h>
#include <cstdint>
#include <math.h>

constexpr int N = 8192;
constexpr int D = 128;
constexpr float SCALE_L2E = 14.4269504088896f;   // 10 * log2(e)

constexpr int NT     = 64;
constexpr int NTILES = 2080;
constexpr int GRID   = 296;                      // 2 CTAs x 148 SMs, all resident

constexpr int ROWB  = 272;
constexpr int ATILE = 128 * ROWB;
constexpr int SMEM_A   = 0;
constexpr int SMEM_B0  = ATILE;
constexpr int SMEM_B1  = 2 * ATILE;
constexpr int SMEM_RED = 3 * ATILE;
constexpr int SMEM_BYTES = 3 * ATILE + 2048;     // 106496 B; 2 CTAs = 208 KB <= 228 KB

__device__ uint4 g_hv[N * D / 8];
__device__ float g_total[N];
__device__ float g_pos[N];
__device__ float g_loss;
__device__ unsigned g_bar;                       // monotonic barrier counter
#define G_H ((__half*)g_hv)

__device__ __forceinline__ uint32_t smem_u32(const void* p) {
    uint32_t a;
    asm("{ .reg .u64 t; cvta.to.shared.u64 t, %1; cvt.u32.u64 %0, t; }"
        : "=r"(a) : "l"(p));
    return a;
}
__device__ __forceinline__ void ldmx4(uint32_t& r0, uint32_t& r1, uint32_t& r2,
                                      uint32_t& r3, uint32_t addr) {
    asm volatile("ldmatrix.sync.aligned.m8n8.x4.shared.b16 {%0,%1,%2,%3}, [%4];"
                 : "=r"(r0), "=r"(r1), "=r"(r2), "=r"(r3) : "r"(addr));
}
__device__ __forceinline__ void mma16816(float* c, uint32_t a0, uint32_t a1,
                                         uint32_t a2, uint32_t a3,
                                         uint32_t b0, uint32_t b1) {
    asm volatile(
        "mma.sync.aligned.m16n8k16.row.col.f32.f16.f16.f32 "
        "{%0,%1,%2,%3}, {%4,%5,%6,%7}, {%8,%9}, {%0,%1,%2,%3};"
        : "+f"(c[0]), "+f"(c[1]), "+f"(c[2]), "+f"(c[3])
        : "r"(a0), "r"(a1), "r"(a2), "r"(a3), "r"(b0), "r"(b1));
}
__device__ __forceinline__ float fast_ex2(float x) {
    float r;
    asm("ex2.approx.ftz.f32 %0, %1;" : "=f"(r) : "f"(x));
    return r;
}
__device__ __forceinline__ void cpa16(uint32_t sdst, const void* gsrc) {
    asm volatile("cp.async.cg.shared.global [%0], [%1], 16;"
                 :: "r"(sdst), "l"(gsrc) : "memory");
}
__device__ __forceinline__ void cpa_commit() {
    asm volatile("cp.async.commit_group;" ::: "memory");
}
__device__ __forceinline__ void cpa_wait0() {
    asm volatile("cp.async.wait_group 0;" ::: "memory");
}

__device__ __forceinline__ void stage_tile(uint32_t sdst, const uint4* gsrc, int tid) {
    #pragma unroll
    for (int it = 0; it < 8; it++) {
        int idx = it * 256 + tid;
        int r = idx >> 4, c = idx & 15;
        cpa16(sdst + r * ROWB + c * 16, gsrc + idx);
    }
}

// replay-safe grid barrier: counter only grows; target = next multiple of GRID
__device__ __forceinline__ void grid_barrier(int tid) {
    __syncthreads();
    if (tid == 0) {
        __threadfence();
        unsigned arrival = atomicAdd(&g_bar, 1u) + 1u;
        unsigned target = ((arrival + GRID - 1u) / GRID) * GRID;
        while (*(volatile unsigned*)&g_bar < target) {}
        __threadfence();
    }
    __syncthreads();
}

// ---------------- single fused persistent kernel ----------------------------
__global__ __launch_bounds__(256, 2) void fused_kernel(
    const float* __restrict__ in, float* __restrict__ out) {
    extern __shared__ char smem[];
    const int tid  = threadIdx.x;
    const int lane = tid & 31;
    const int wid  = tid >> 5;
    const int wrow = wid >> 2;
    const int wcol = wid & 3;
    const uint32_t sb = smem_u32(smem);
    float* sred = (float*)(smem + SMEM_RED);

    // ================= phase 1: normalize -> fp16, zero accs ================
    {
        const int gw = blockIdx.x * 8 + wid;           // 0..2367 global warp
        for (int r = gw; r < N; r += GRID * 8) {
            const float4 v = ((const float4*)(in + (size_t)r * D))[lane];
            float ss = v.x * v.x + v.y * v.y + v.z * v.z + v.w * v.w;
            #pragma unroll
            for (int o = 16; o; o >>= 1)
                ss += __shfl_xor_sync(0xffffffffu, ss, o);
            float sc = rsqrtf(ss);
            union { __half2 h[2]; uint2 u; } pk;
            pk.h[0] = __floats2half2_rn(v.x * sc, v.y * sc);
            pk.h[1] = __floats2half2_rn(v.z * sc, v.w * sc);
            ((uint2*)g_hv)[r * 32 + lane] = pk.u;
            if (lane == 0) { g_total[r] = 0.f; g_pos[r] = 0.f; }
        }
        if (blockIdx.x == 0 && tid == 0) g_loss = 0.f;
    }
    grid_barrier(tid);

    // ================= phase 2: persistent HMMA Gram =========================
    int t  = (int)((long long)blockIdx.x * NTILES / GRID);
    int t1 = (int)((long long)(blockIdx.x + 1) * NTILES / GRID);
    int br = 0, base = 0;
    while (t >= base + (NT - br)) { base += NT - br; br++; }
    int bc = br + (t - base);

    uint32_t aAddr[4];
    #pragma unroll
    for (int i = 0; i < 4; i++)
        aAddr[i] = sb + SMEM_A +
                   (wrow * 64 + i * 16 + (lane & 15)) * ROWB + (lane >> 4) * 16;
    const uint32_t bLane = (wcol * 32 + (lane & 7) + ((lane >> 4) & 1) * 8) * ROWB +
                           ((lane >> 3) & 1) * 16;

    while (t < t1) {
        stage_tile(sb + SMEM_A, (const uint4*)(G_H + (size_t)br * 128 * D), tid);
        stage_tile(sb + SMEM_B0, (const uint4*)(G_H + (size_t)bc * 128 * D), tid);
        cpa_commit(); cpa_wait0();
        __syncthreads();

        float rs_acc[8];
        #pragma unroll
        for (int q = 0; q < 8; q++) rs_acc[q] = 0.f;
        int buf = 0;

        for (;;) {
            const bool diag = (bc == br);
            const bool next_same = (t + 1 < t1) && (bc + 1 < NT);
            if (next_same) {
                stage_tile(sb + (buf ? SMEM_B0 : SMEM_B1),
                           (const uint4*)(G_H + (size_t)(bc + 1) * 128 * D), tid);
                cpa_commit();
            }

            const uint32_t bbase = sb + (buf ? SMEM_B1 : SMEM_B0) + bLane;
            float acc[4][4][4];
            #pragma unroll
            for (int i = 0; i < 4; i++)
                #pragma unroll
                for (int j = 0; j < 4; j++)
                    #pragma unroll
                    for (int r = 0; r < 4; r++) acc[i][j][r] = 0.f;

            uint32_t bf[2][8];
            ldmx4(bf[0][0], bf[0][1], bf[0][2], bf[0][3], bbase);
            ldmx4(bf[0][4], bf[0][5], bf[0][6], bf[0][7], bbase + 16 * ROWB);
            #pragma unroll
            for (int ks = 0; ks < 8; ks++) {
                const int cur = ks & 1, nxt = cur ^ 1;
                if (ks < 7) {
                    ldmx4(bf[nxt][0], bf[nxt][1], bf[nxt][2], bf[nxt][3],
                          bbase + (ks + 1) * 32);
                    ldmx4(bf[nxt][4], bf[nxt][5], bf[nxt][6], bf[nxt][7],
                          bbase + 16 * ROWB + (ks + 1) * 32);
                }
                #pragma unroll
                for (int i = 0; i < 4; i++) {
                    uint32_t a0, a1, a2, a3;
                    ldmx4(a0, a1, a2, a3, aAddr[i] + ks * 32);
                    #pragma unroll
                    for (int j = 0; j < 4; j++)
                        mma16816(acc[i][j], a0, a1, a2, a3,
                                 bf[cur][j * 2], bf[cur][j * 2 + 1]);
                }
            }

            const unsigned m = 0xffffffffu;
            if (diag) {
                float rt[8];
                #pragma unroll
                for (int q = 0; q < 8; q++) rt[q] = 0.f;
                #pragma unroll
                for (int i = 0; i < 4; i++)
                    #pragma unroll
                    for (int j = 0; j < 4; j++) {
                        rt[i*2]   += fast_ex2(acc[i][j][0] * SCALE_L2E) +
                                     fast_ex2(acc[i][j][1] * SCALE_L2E);
                        rt[i*2+1] += fast_ex2(acc[i][j][2] * SCALE_L2E) +
                                     fast_ex2(acc[i][j][3] * SCALE_L2E);
                    }
                #pragma unroll
                for (int q = 0; q < 8; q++) {
                    rt[q] += __shfl_xor_sync(m, rt[q], 1);
                    rt[q] += __shfl_xor_sync(m, rt[q], 2);
                    if ((lane & 3) == 0) rs_acc[q] += rt[q];   // flush re-reduces
                }
                if ((lane & 3) == 0) {
                    #pragma unroll
                    for (int i = 0; i < 4; i++)
                        #pragma unroll
                        for (int h = 0; h < 2; h++)
                            sred[wcol*128 + wrow*64 + i*16 + (lane>>2) + h*8] = rt[i*2+h];
                }
                cpa_wait0();
                __syncthreads();
                if (tid < 128) {
                    int h = tid >> 6;
                    g_pos[br * 128 + tid] =
                        sred[(2*h)*128 + tid] + sred[(2*h+1)*128 + tid];
                }
                __syncthreads();
            } else {
                float cs[8];
                #pragma unroll
                for (int q = 0; q < 8; q++) cs[q] = 0.f;
                #pragma unroll
                for (int i = 0; i < 4; i++)
                    #pragma unroll
                    for (int j = 0; j < 4; j++) {
                        float e0 = fast_ex2(acc[i][j][0] * SCALE_L2E);
                        float e1 = fast_ex2(acc[i][j][1] * SCALE_L2E);
                        float e2 = fast_ex2(acc[i][j][2] * SCALE_L2E);
                        float e3 = fast_ex2(acc[i][j][3] * SCALE_L2E);
                        rs_acc[i*2]   += e0 + e1;
                        rs_acc[i*2+1] += e2 + e3;
                        cs[j*2]   += e0 + e2;
                        cs[j*2+1] += e1 + e3;
                    }
                #pragma unroll
                for (int q = 0; q < 8; q++) {
                    cs[q] += __shfl_xor_sync(m, cs[q], 4);
                    cs[q] += __shfl_xor_sync(m, cs[q], 8);
                    cs[q] += __shfl_xor_sync(m, cs[q], 16);
                }
                if (lane < 4) {
                    const int colbase = bc * 128 + wcol * 32 + lane * 2;
                    #pragma unroll
                    for (int j = 0; j < 4; j++) {
                        atomicAdd(&g_total[colbase + j * 8],     cs[j*2]);
                        atomicAdd(&g_total[colbase + j * 8 + 1], cs[j*2+1]);
                    }
                }
                cpa_wait0();
                __syncthreads();
            }

            t++; bc++;
            if (!next_same) break;
            buf ^= 1;
        }

        // flush accumulated row sums for band br
        __syncthreads();
        const unsigned m = 0xffffffffu;
        float rf[8];
        #pragma unroll
        for (int q = 0; q < 8; q++) {
            float v = rs_acc[q];
            v += __shfl_xor_sync(m, v, 1);
            v += __shfl_xor_sync(m, v, 2);
            rf[q] = v;
        }
        if ((lane & 3) == 0) {
            #pragma unroll
            for (int i = 0; i < 4; i++)
                #pragma unroll
                for (int h = 0; h < 2; h++)
                    sred[wcol*128 + wrow*64 + i*16 + (lane>>2) + h*8] = rf[i*2+h];
        }
        __syncthreads();
        if (tid < 128)
            atomicAdd(&g_total[br * 128 + tid],
                      sred[tid] + sred[128+tid] + sred[256+tid] + sred[384+tid]);
        __syncthreads();

        if (t < t1 && bc >= NT) { br++; bc = br; }
    }

    // ================= phase 3: loss =========================================
    grid_barrier(tid);                             // all g_total/g_pos complete
    {
        const int gtid = blockIdx.x * 256 + tid;
        float s = 0.f;
        if (gtid < N)
            s = __logf(g_total[gtid]) - __logf(g_pos[gtid]);
        #pragma unroll
        for (int o = 16; o; o >>= 1) s += __shfl_xor_sync(0xffffffffu, s, o);
        __shared__ float wsum[8];
        if (lane == 0) wsum[wid] = s;
        __syncthreads();
        if (tid == 0 && blockIdx.x * 256 < N) {
            float bs = 0.f;
            #pragma unroll
            for (int i = 0; i < 8; i++) bs += wsum[i];
            atomicAdd(&g_loss, bs);
        }
    }
    grid_barrier(tid);
    if (blockIdx.x == 0 && tid == 0)
        out[0] = g_loss / (float)N;
}

// ---------------- launch ----------------------------------------------------
extern "C" void kernel_launch(void* const* d_in, const int* in_sizes, int n_in,
                              void* d_out, int out_size) {
    const float* feature = (const float*)d_in[0];
    cudaFuncSetAttribute(fused_kernel,
                         cudaFuncAttributeMaxDynamicSharedMemorySize, SMEM_BYTES);
    fused_kernel<<<GRID, 256, SMEM_BYTES>>>(feature, (float*)d_out);
}